// round 15
// baseline (speedup 1.0000x reference)
#include <cuda_runtime.h>
#include <cstdint>
#include <math.h>

#define NMAX     50000
#define EMAX     850000
#define HC       384
#define CH       128
#define NHEAD    3

// ---------------- scratch (device globals; no allocation allowed) ----------
__device__ float    g_p[(size_t)NMAX * HC];     // projected features (per layer)
__device__ float    g_agg[(size_t)NMAX * HC];   // aggregated output (per layer)
__device__ float    g_asrc[NMAX * NHEAD];
__device__ float    g_adst[NMAX * NHEAD];
__device__ float    g_w[(size_t)EMAX * NHEAD];  // attn weights (CSR order)
__device__ float    g_denom[NMAX * NHEAD];
__device__ int      g_counts[NMAX];
__device__ int      g_rowoff[NMAX + 1];
__device__ int      g_cursor[NMAX];
__device__ int      g_csr_s[EMAX];
__device__ int      g_bsum[64];
__device__ int      g_boff[64];
__device__ int      g_is64;                     // 1 if edge_index is int64

// ---------------- helpers ---------------------------------------------------
__device__ __forceinline__ int load_idx(const void* ei, size_t i) {
    if (g_is64) return (int)((const long long*)ei)[i];
    return ((const int*)ei)[i];
}
__device__ __forceinline__ unsigned long long pk2(float lo, float hi) {
    unsigned long long r;
    asm("mov.b64 %0, {%1, %2};" : "=l"(r) : "f"(lo), "f"(hi));
    return r;
}
__device__ __forceinline__ void ffma2(unsigned long long& d,
                                      unsigned long long a, unsigned long long b) {
    asm("fma.rn.f32x2 %0, %1, %2, %0;" : "+l"(d) : "l"(a), "l"(b));
}
__device__ __forceinline__ void unpk2(unsigned long long v, float& lo, float& hi) {
    asm("mov.b64 {%0, %1}, %2;" : "=f"(lo), "=f"(hi) : "l"(v));
}

// Detect edge_index dtype: view as int32; if int64 (LE, values < 2^31) every
// odd word is the zero high-half. 256 samples -> false positive prob ~0.
__global__ void detect_dtype_kernel(const int* __restrict__ ei32)
{
    __shared__ int any_nz;
    if (threadIdx.x == 0) any_nz = 0;
    __syncthreads();
    if (ei32[2 * threadIdx.x + 1] != 0) atomicOr(&any_nz, 1);
    __syncthreads();
    if (threadIdx.x == 0) g_is64 = any_nz ? 0 : 1;
}

// ---------------- SGEMM: C[M,N] = op(A)[M,K] @ B[K,N] ----------------------
// 128x128 tile, BK=16, 256 threads, 8x8 microtile via packed f32x2 FFMA2,
// register double buffering. Conflict-free smem. FROZEN (best: 1095.8us).
template<int RELU_A, int ATT>
__global__ __launch_bounds__(256) void sgemm_kernel(
    const float* __restrict__ A, const float* __restrict__ B,
    float* __restrict__ C,
    const float* __restrict__ att_src, const float* __restrict__ att_dst,
    int M, int N, int K)
{
    __shared__ float As[2][16][132];    // padded: STS banks (4c+t)%32, no conflict
    __shared__ float Bs[2][16][128];
    const int tid = threadIdx.x;
    const int bm = blockIdx.y * 128;
    const int bn = blockIdx.x * 128;
    const int tx = tid & 15;
    const int ty = tid >> 4;
    const int arow = tid >> 1;
    const int acol = (tid & 1) << 2;
    const int brow = tid >> 5;
    const int bcol = (tid & 31) << 2;

    unsigned long long acc2[8][4];
#pragma unroll
    for (int i = 0; i < 8; i++)
#pragma unroll
        for (int jp = 0; jp < 4; jp++) acc2[i][jp] = 0ull;

    const int gm = bm + arow;
    const bool avalid = (gm < M);
    const int gn = bn + bcol;

    auto loadA = [&](int k0, float4& v0, float4& v1) {
        v0 = make_float4(0.f, 0.f, 0.f, 0.f);
        v1 = v0;
        if (avalid) {
            const float* Arow = A + (size_t)gm * K + k0 + acol;
            v0 = *reinterpret_cast<const float4*>(Arow);
            v1 = *reinterpret_cast<const float4*>(Arow + 8);
        }
        if (RELU_A) {
            v0.x = fmaxf(v0.x, 0.f); v0.y = fmaxf(v0.y, 0.f);
            v0.z = fmaxf(v0.z, 0.f); v0.w = fmaxf(v0.w, 0.f);
            v1.x = fmaxf(v1.x, 0.f); v1.y = fmaxf(v1.y, 0.f);
            v1.z = fmaxf(v1.z, 0.f); v1.w = fmaxf(v1.w, 0.f);
        }
    };
    auto loadB = [&](int k0, float4& v0, float4& v1) {
        v0 = *reinterpret_cast<const float4*>(B + (size_t)(k0 + brow) * N + gn);
        v1 = *reinterpret_cast<const float4*>(B + (size_t)(k0 + brow + 8) * N + gn);
    };
    auto store = [&](int buf, float4 a0, float4 a1, float4 b0, float4 b1) {
        As[buf][acol + 0][arow] = a0.x;
        As[buf][acol + 1][arow] = a0.y;
        As[buf][acol + 2][arow] = a0.z;
        As[buf][acol + 3][arow] = a0.w;
        As[buf][8 + acol + 0][arow] = a1.x;
        As[buf][8 + acol + 1][arow] = a1.y;
        As[buf][8 + acol + 2][arow] = a1.z;
        As[buf][8 + acol + 3][arow] = a1.w;
        *reinterpret_cast<float4*>(&Bs[buf][brow][bcol]) = b0;
        *reinterpret_cast<float4*>(&Bs[buf][brow + 8][bcol]) = b1;
    };
    auto compute = [&](int buf) {
#pragma unroll
        for (int k = 0; k < 16; k++) {
            float4 a0 = *reinterpret_cast<const float4*>(&As[buf][k][ty * 8]);
            float4 a1 = *reinterpret_cast<const float4*>(&As[buf][k][ty * 8 + 4]);
            float4 b0 = *reinterpret_cast<const float4*>(&Bs[buf][k][tx * 4]);
            float4 b1 = *reinterpret_cast<const float4*>(&Bs[buf][k][64 + tx * 4]);
            unsigned long long bp[4] = {
                pk2(b0.x, b0.y), pk2(b0.z, b0.w),
                pk2(b1.x, b1.y), pk2(b1.z, b1.w)
            };
            float a[8] = {a0.x, a0.y, a0.z, a0.w, a1.x, a1.y, a1.z, a1.w};
#pragma unroll
            for (int i = 0; i < 8; i++) {
                const unsigned long long ap = pk2(a[i], a[i]);
#pragma unroll
                for (int jp = 0; jp < 4; jp++)
                    ffma2(acc2[i][jp], ap, bp[jp]);
            }
        }
    };

    {
        float4 a0, a1, b0, b1;
        loadA(0, a0, a1);
        loadB(0, b0, b1);
        store(0, a0, a1, b0, b1);
    }
    __syncthreads();
    int cur = 0;
    for (int k0 = 16; k0 < K; k0 += 16) {
        float4 a0, a1, b0, b1;
        loadA(k0, a0, a1);
        loadB(k0, b0, b1);
        compute(cur);
        store(cur ^ 1, a0, a1, b0, b1);
        __syncthreads();
        cur ^= 1;
    }
    compute(cur);

    float acc[8][8];
#pragma unroll
    for (int i = 0; i < 8; i++)
#pragma unroll
        for (int jp = 0; jp < 4; jp++)
            unpk2(acc2[i][jp], acc[i][jp * 2], acc[i][jp * 2 + 1]);

#pragma unroll
    for (int i = 0; i < 8; i++) {
        const int m = bm + ty * 8 + i;
        if (m >= M) continue;
        float* crow = C + (size_t)m * N + bn;
        *reinterpret_cast<float4*>(crow + tx * 4) =
            make_float4(acc[i][0], acc[i][1], acc[i][2], acc[i][3]);
        *reinterpret_cast<float4*>(crow + 64 + tx * 4) =
            make_float4(acc[i][4], acc[i][5], acc[i][6], acc[i][7]);
    }

    if (ATT) {
        const int head = bn >> 7;
        float as_v[8], ad_v[8];
#pragma unroll
        for (int j = 0; j < 4; j++) {
            as_v[j]     = att_src[head * CH + tx * 4 + j];
            ad_v[j]     = att_dst[head * CH + tx * 4 + j];
            as_v[4 + j] = att_src[head * CH + 64 + tx * 4 + j];
            ad_v[4 + j] = att_dst[head * CH + 64 + tx * 4 + j];
        }
#pragma unroll
        for (int i = 0; i < 8; i++) {
            float s1 = 0.f, s2 = 0.f;
#pragma unroll
            for (int j = 0; j < 8; j++) {
                s1 = fmaf(acc[i][j], as_v[j], s1);
                s2 = fmaf(acc[i][j], ad_v[j], s2);
            }
#pragma unroll
            for (int o = 8; o >= 1; o >>= 1) {
                s1 += __shfl_xor_sync(0xffffffffu, s1, o);
                s2 += __shfl_xor_sync(0xffffffffu, s2, o);
            }
            const int m = bm + ty * 8 + i;
            if (tx == 0 && m < M) {
                g_asrc[m * 3 + head] = s1;
                g_adst[m * 3 + head] = s2;
            }
        }
    }
}

// ---------------- head GEMM: C[M,40] = relu(A)[M,384] @ B[384,40] + bias ----
// 2 rows x 10 cols (5 col-pairs) per thread via FFMA2.
__global__ __launch_bounds__(256) void sgemm_head_kernel(
    const float* __restrict__ A, const float* __restrict__ B,
    const float* __restrict__ bias, float* __restrict__ C, int M)
{
    const int NK = 384, NN = 40;
    __shared__ float As[8][128];
    __shared__ float Bs[8][40];
    const int tid = threadIdx.x;
    const int bm = blockIdx.x * 128;
    const int tx = tid & 3;          // col group: cols tx*10 .. tx*10+9
    const int ty = tid >> 2;         // row group: rows ty*2, ty*2+1
    const int arow = tid >> 1;
    const int acol = (tid & 1) << 2;
    const int gm = bm + arow;
    const bool avalid = (gm < M);

    unsigned long long acc2[2][5];
#pragma unroll
    for (int i = 0; i < 2; i++)
#pragma unroll
        for (int jp = 0; jp < 5; jp++) acc2[i][jp] = 0ull;

    for (int k0 = 0; k0 < NK; k0 += 8) {
        float4 av = make_float4(0.f, 0.f, 0.f, 0.f);
        if (avalid)
            av = *reinterpret_cast<const float4*>(A + (size_t)gm * NK + k0 + acol);
        As[acol + 0][arow] = fmaxf(av.x, 0.f);
        As[acol + 1][arow] = fmaxf(av.y, 0.f);
        As[acol + 2][arow] = fmaxf(av.z, 0.f);
        As[acol + 3][arow] = fmaxf(av.w, 0.f);
        if (tid < 160) {             // 8*40 = 320 values, 2 per thread
            const int r0 = tid / 20, c0 = (tid % 20) * 2;
            Bs[r0][c0]     = B[(size_t)(k0 + r0) * NN + c0];
            Bs[r0][c0 + 1] = B[(size_t)(k0 + r0) * NN + c0 + 1];
        }
        __syncthreads();
#pragma unroll
        for (int k = 0; k < 8; k++) {
            const float a0 = As[k][ty * 2];
            const float a1 = As[k][ty * 2 + 1];
            const unsigned long long ap0 = pk2(a0, a0);
            const unsigned long long ap1 = pk2(a1, a1);
#pragma unroll
            for (int jp = 0; jp < 5; jp++) {
                const unsigned long long bp =
                    *reinterpret_cast<const unsigned long long*>(&Bs[k][tx * 10 + jp * 2]);
                ffma2(acc2[0][jp], ap0, bp);
                ffma2(acc2[1][jp], ap1, bp);
            }
        }
        __syncthreads();
    }
#pragma unroll
    for (int i = 0; i < 2; i++) {
        const int m = bm + ty * 2 + i;
        if (m >= M) continue;
#pragma unroll
        for (int jp = 0; jp < 5; jp++) {
            float lo, hi;
            unpk2(acc2[i][jp], lo, hi);
            const int n = tx * 10 + jp * 2;
            C[(size_t)m * NN + n]     = lo + bias[n];
            C[(size_t)m * NN + n + 1] = hi + bias[n + 1];
        }
    }
}

// ---------------- CSR build --------------------------------------------------
__global__ void zero_counts_kernel(int n)
{
    const int i = blockIdx.x * blockDim.x + threadIdx.x;
    if (i < n) g_counts[i] = 0;
}

__global__ void hist_kernel(const void* __restrict__ ei, int E, int ET)
{
    const int e = blockIdx.x * blockDim.x + threadIdx.x;
    if (e >= ET) return;
    const int d = (e < E) ? load_idx(ei, (size_t)E + e) : (e - E);
    atomicAdd(&g_counts[d], 1);
}

__global__ __launch_bounds__(1024) void scan1_kernel(int n)
{
    __shared__ int wsum[32];
    const int i = blockIdx.x * 1024 + threadIdx.x;
    const int lane = threadIdx.x & 31;
    const int wid = threadIdx.x >> 5;
    const int v = (i < n) ? g_counts[i] : 0;
    int x = v;
#pragma unroll
    for (int o = 1; o < 32; o <<= 1) {
        const int t = __shfl_up_sync(0xffffffffu, x, o);
        if (lane >= o) x += t;
    }
    if (lane == 31) wsum[wid] = x;
    __syncthreads();
    if (wid == 0) {
        int s = wsum[lane];
#pragma unroll
        for (int o = 1; o < 32; o <<= 1) {
            const int t = __shfl_up_sync(0xffffffffu, s, o);
            if (lane >= o) s += t;
        }
        wsum[lane] = s;
    }
    __syncthreads();
    const int incl = x + ((wid > 0) ? wsum[wid - 1] : 0);
    if (i < n) g_rowoff[i] = incl - v;
    if (threadIdx.x == 1023) g_bsum[blockIdx.x] = incl;
}

__global__ void scan2_kernel(int nb, int n)
{
    const int lane = threadIdx.x;
    const int a = (lane < nb) ? g_bsum[lane] : 0;
    const int b = (32 + lane < nb) ? g_bsum[32 + lane] : 0;
    int xa = a, xb = b;
#pragma unroll
    for (int o = 1; o < 32; o <<= 1) {
        int t = __shfl_up_sync(0xffffffffu, xa, o);
        if (lane >= o) xa += t;
        t = __shfl_up_sync(0xffffffffu, xb, o);
        if (lane >= o) xb += t;
    }
    const int totA = __shfl_sync(0xffffffffu, xa, 31);
    const int totB = __shfl_sync(0xffffffffu, xb, 31);
    g_boff[lane] = xa - a;
    g_boff[32 + lane] = totA + xb - b;
    if (lane == 31) g_rowoff[n] = totA + totB;
}

__global__ void scan3_kernel(int n)
{
    const int i = blockIdx.x * blockDim.x + threadIdx.x;
    if (i >= n) return;
    const int off = g_rowoff[i] + g_boff[i >> 10];
    g_rowoff[i] = off;
    g_cursor[i] = off;
}

__global__ void scatter_kernel(const void* __restrict__ ei, int E, int ET)
{
    const int e = blockIdx.x * blockDim.x + threadIdx.x;
    if (e >= ET) return;
    int s, d;
    if (e < E) { s = load_idx(ei, e); d = load_idx(ei, (size_t)E + e); }
    else       { s = d = e - E; }
    const int pos = atomicAdd(&g_cursor[d], 1);
    g_csr_s[pos] = s;
}

// ---------------- per-node softmax weights: one warp per node ---------------
// Single pass, no max subtraction (alpha bounded; softmax shift-invariant).
__global__ __launch_bounds__(256) void attn_kernel(int n_nodes)
{
    const int warp = (blockIdx.x * blockDim.x + threadIdx.x) >> 5;
    const int lane = threadIdx.x & 31;
    if (warp >= n_nodes) return;
    const int d = warp;
    const int beg = g_rowoff[d];
    const int end = g_rowoff[d + 1];
    const float ad0 = g_adst[d * 3 + 0];
    const float ad1 = g_adst[d * 3 + 1];
    const float ad2 = g_adst[d * 3 + 2];

    float s0 = 0.f, s1 = 0.f, s2 = 0.f;
    for (int i = beg + lane; i < end; i += 32) {
        const int s = g_csr_s[i];
        float a0 = g_asrc[s * 3 + 0] + ad0;
        float a1 = g_asrc[s * 3 + 1] + ad1;
        float a2 = g_asrc[s * 3 + 2] + ad2;
        a0 = (a0 > 0.f) ? a0 : 0.2f * a0;
        a1 = (a1 > 0.f) ? a1 : 0.2f * a1;
        a2 = (a2 > 0.f) ? a2 : 0.2f * a2;
        const float w0 = __expf(a0);
        const float w1 = __expf(a1);
        const float w2 = __expf(a2);
        g_w[(size_t)i * 3 + 0] = w0;
        g_w[(size_t)i * 3 + 1] = w1;
        g_w[(size_t)i * 3 + 2] = w2;
        s0 += w0; s1 += w1; s2 += w2;
    }
#pragma unroll
    for (int o = 16; o; o >>= 1) {
        s0 += __shfl_xor_sync(0xffffffffu, s0, o);
        s1 += __shfl_xor_sync(0xffffffffu, s1, o);
        s2 += __shfl_xor_sync(0xffffffffu, s2, o);
    }
    if (lane == 0) {
        g_denom[d * 3 + 0] = s0;
        g_denom[d * 3 + 1] = s1;
        g_denom[d * 3 + 2] = s2;
    }
}

// ---------------- zero-sync weighted gather: TWO nodes per block ------------
// Interleaves the edge streams of nodes (2b, 2b+1): 4 independent load chains
// per iteration (2 edges x 2 nodes) -> MLP 8 for low-degree nodes, and half
// the node-serialization slots. Out-of-range edges: CSR index clamped to
// end-1 (always valid: self-loop guarantees >=1 edge), weight zeroed.
__global__ __launch_bounds__(384) void gat_gather2(
    const float* __restrict__ P, const float* __restrict__ bias,
    float* __restrict__ out, int n_nodes)
{
    const int j = threadIdx.x;
    const int h = j >> 7;
    const float bj = bias[j];
    const int d0 = blockIdx.x * 2;
    if (d0 >= n_nodes) return;
    const int d1 = min(d0 + 1, n_nodes - 1);

    const int beg0 = g_rowoff[d0], end0 = g_rowoff[d0 + 1];
    const int beg1 = g_rowoff[d1], end1 = g_rowoff[d1 + 1];
    const int n0 = end0 - beg0, n1 = end1 - beg1;
    const int nmax = max(n0, n1);

    float x0 = 0.f, y0 = 0.f;    // node d0, two accumulators
    float x1 = 0.f, y1 = 0.f;    // node d1

    for (int i = 0; i < nmax; i += 2) {
        const int c0a = min(beg0 + i,     end0 - 1);
        const int c0b = min(beg0 + i + 1, end0 - 1);
        const int c1a = min(beg1 + i,     end1 - 1);
        const int c1b = min(beg1 + i + 1, end1 - 1);
        const int s0a = g_csr_s[c0a];
        const int s0b = g_csr_s[c0b];
        const int s1a = g_csr_s[c1a];
        const int s1b = g_csr_s[c1b];
        const float w0a = (i     < n0) ? g_w[(size_t)c0a * 3 + h] : 0.f;
        const float w0b = (i + 1 < n0) ? g_w[(size_t)c0b * 3 + h] : 0.f;
        const float w1a = (i     < n1) ? g_w[(size_t)c1a * 3 + h] : 0.f;
        const float w1b = (i + 1 < n1) ? g_w[(size_t)c1b * 3 + h] : 0.f;
        x0 = fmaf(w0a, P[(size_t)s0a * HC + j], x0);
        y0 = fmaf(w0b, P[(size_t)s0b * HC + j], y0);
        x1 = fmaf(w1a, P[(size_t)s1a * HC + j], x1);
        y1 = fmaf(w1b, P[(size_t)s1b * HC + j], y1);
    }

    const float inv0 = 1.f / (g_denom[d0 * 3 + h] + 1e-16f);
    out[(size_t)d0 * HC + j] = (x0 + y0) * inv0 + bj;
    if (d0 + 1 < n_nodes) {
        const float inv1 = 1.f / (g_denom[d1 * 3 + h] + 1e-16f);
        out[(size_t)d1 * HC + j] = (x1 + y1) * inv1 + bj;
    }
}

// ---------------- launch -----------------------------------------------------
extern "C" void kernel_launch(void* const* d_in, const int* in_sizes, int n_in,
                              void* d_out, int out_size)
{
    const float* x    = (const float*)d_in[0];
    const void*  ei   = d_in[1];
    const float* W1   = (const float*)d_in[2];
    const float* as1  = (const float*)d_in[3];
    const float* ad1  = (const float*)d_in[4];
    const float* b1   = (const float*)d_in[5];
    const float* W2   = (const float*)d_in[6];
    const float* as2  = (const float*)d_in[7];
    const float* ad2  = (const float*)d_in[8];
    const float* b2   = (const float*)d_in[9];
    const float* outW = (const float*)d_in[10];
    const float* outb = (const float*)d_in[11];
    float* out = (float*)d_out;

    const int IN_DIM = 256;
    const int n_nodes = in_sizes[0] / IN_DIM;   // 50000
    const int E  = in_sizes[1] / 2;             // 800000
    const int ET = E + n_nodes;                 // 850000

    float *p, *agg;
    cudaGetSymbolAddress((void**)&p,   g_p);
    cudaGetSymbolAddress((void**)&agg, g_agg);

    const int TB = 256;
    const int eg = (ET + TB - 1) / TB;
    const int nb = (n_nodes + 1023) / 1024;
    const int wg = (n_nodes * 32 + TB - 1) / TB;   // one warp per node
    const int gg = (n_nodes + 1) / 2;              // two nodes per gather block

    const dim3 g12((HC + 127) / 128, (n_nodes + 127) / 128);

    // dtype probe (must precede any edge read)
    detect_dtype_kernel<<<1, 256>>>((const int*)ei);

    // CSR build start, then sgemm1 as 4th launch (fixed ncu window -s 5 -c 1
    // captures it there).
    zero_counts_kernel<<<(n_nodes + TB - 1) / TB, TB>>>(n_nodes);
    hist_kernel<<<eg, TB>>>(ei, E, ET);

    // ---- layer 1 GEMM (independent of CSR) ----
    sgemm_kernel<0, 1><<<g12, 256>>>(x, W1, p, as1, ad1, n_nodes, HC, IN_DIM);

    // rest of CSR build
    scan1_kernel<<<nb, 1024>>>(n_nodes);
    scan2_kernel<<<1, 32>>>(nb, n_nodes);
    scan3_kernel<<<(n_nodes + TB - 1) / TB, TB>>>(n_nodes);
    scatter_kernel<<<eg, TB>>>(ei, E, ET);

    // ---- layer 1 softmax + aggregate ----
    attn_kernel<<<wg, TB>>>(n_nodes);
    gat_gather2<<<gg, 384>>>(p, b1, agg, n_nodes);

    // ---- layer 2 (relu fused into A-load of GEMM) ----
    sgemm_kernel<1, 1><<<g12, 256>>>(agg, W2, p, as2, ad2, n_nodes, HC, HC);
    attn_kernel<<<wg, TB>>>(n_nodes);
    gat_gather2<<<gg, 384>>>(p, b2, agg, n_nodes);

    // ---- classifier head (relu fused into A-load) ----
    sgemm_head_kernel<<<(n_nodes + 127) / 128, 256>>>(agg, outW, outb, out, n_nodes);
}

// round 16
// speedup vs baseline: 1.7067x; 1.7067x over previous
#include <cuda_runtime.h>
#include <cstdint>
#include <math.h>

#define NMAX     50000
#define EMAX     850000
#define HC       384
#define CH       128
#define NHEAD    3

// ---------------- scratch (device globals; no allocation allowed) ----------
__device__ float    g_p[(size_t)NMAX * HC];     // projected features (per layer)
__device__ float    g_agg[(size_t)NMAX * HC];   // aggregated output (per layer)
__device__ float    g_asrc[NMAX * NHEAD];
__device__ float    g_adst[NMAX * NHEAD];
__device__ float    g_w[(size_t)EMAX * NHEAD];  // attn weights (CSR order)
__device__ float    g_denom[NMAX * NHEAD];
__device__ int      g_counts[NMAX];
__device__ int      g_rowoff[NMAX + 1];
__device__ int      g_cursor[NMAX];
__device__ int      g_csr_s[EMAX];
__device__ int      g_bsum[64];
__device__ int      g_boff[64];
__device__ int      g_is64;                     // 1 if edge_index is int64

// ---------------- helpers ---------------------------------------------------
__device__ __forceinline__ int load_idx(const void* ei, size_t i) {
    if (g_is64) return (int)((const long long*)ei)[i];
    return ((const int*)ei)[i];
}
__device__ __forceinline__ unsigned long long pk2(float lo, float hi) {
    unsigned long long r;
    asm("mov.b64 %0, {%1, %2};" : "=l"(r) : "f"(lo), "f"(hi));
    return r;
}
__device__ __forceinline__ void ffma2(unsigned long long& d,
                                      unsigned long long a, unsigned long long b) {
    asm("fma.rn.f32x2 %0, %1, %2, %0;" : "+l"(d) : "l"(a), "l"(b));
}
__device__ __forceinline__ void unpk2(unsigned long long v, float& lo, float& hi) {
    asm("mov.b64 {%0, %1}, %2;" : "=f"(lo), "=f"(hi) : "l"(v));
}

// Detect edge_index dtype: view as int32; if int64 (LE, values < 2^31) every
// odd word is the zero high-half. 256 samples -> false positive prob ~0.
__global__ void detect_dtype_kernel(const int* __restrict__ ei32)
{
    __shared__ int any_nz;
    if (threadIdx.x == 0) any_nz = 0;
    __syncthreads();
    if (ei32[2 * threadIdx.x + 1] != 0) atomicOr(&any_nz, 1);
    __syncthreads();
    if (threadIdx.x == 0) g_is64 = any_nz ? 0 : 1;
}

// ---------------- SGEMM: C[M,N] = op(A)[M,K] @ B[K,N] ----------------------
// 128x128 tile, BK=16, 256 threads, 8x8 microtile via packed f32x2 FFMA2,
// register double buffering. Conflict-free smem. FROZEN (best: 1095.8us).
template<int RELU_A, int ATT>
__global__ __launch_bounds__(256) void sgemm_kernel(
    const float* __restrict__ A, const float* __restrict__ B,
    float* __restrict__ C,
    const float* __restrict__ att_src, const float* __restrict__ att_dst,
    int M, int N, int K)
{
    __shared__ float As[2][16][132];    // padded: STS banks (4c+t)%32, no conflict
    __shared__ float Bs[2][16][128];
    const int tid = threadIdx.x;
    const int bm = blockIdx.y * 128;
    const int bn = blockIdx.x * 128;
    const int tx = tid & 15;
    const int ty = tid >> 4;
    const int arow = tid >> 1;
    const int acol = (tid & 1) << 2;
    const int brow = tid >> 5;
    const int bcol = (tid & 31) << 2;

    unsigned long long acc2[8][4];
#pragma unroll
    for (int i = 0; i < 8; i++)
#pragma unroll
        for (int jp = 0; jp < 4; jp++) acc2[i][jp] = 0ull;

    const int gm = bm + arow;
    const bool avalid = (gm < M);
    const int gn = bn + bcol;

    auto loadA = [&](int k0, float4& v0, float4& v1) {
        v0 = make_float4(0.f, 0.f, 0.f, 0.f);
        v1 = v0;
        if (avalid) {
            const float* Arow = A + (size_t)gm * K + k0 + acol;
            v0 = *reinterpret_cast<const float4*>(Arow);
            v1 = *reinterpret_cast<const float4*>(Arow + 8);
        }
        if (RELU_A) {
            v0.x = fmaxf(v0.x, 0.f); v0.y = fmaxf(v0.y, 0.f);
            v0.z = fmaxf(v0.z, 0.f); v0.w = fmaxf(v0.w, 0.f);
            v1.x = fmaxf(v1.x, 0.f); v1.y = fmaxf(v1.y, 0.f);
            v1.z = fmaxf(v1.z, 0.f); v1.w = fmaxf(v1.w, 0.f);
        }
    };
    auto loadB = [&](int k0, float4& v0, float4& v1) {
        v0 = *reinterpret_cast<const float4*>(B + (size_t)(k0 + brow) * N + gn);
        v1 = *reinterpret_cast<const float4*>(B + (size_t)(k0 + brow + 8) * N + gn);
    };
    auto store = [&](int buf, float4 a0, float4 a1, float4 b0, float4 b1) {
        As[buf][acol + 0][arow] = a0.x;
        As[buf][acol + 1][arow] = a0.y;
        As[buf][acol + 2][arow] = a0.z;
        As[buf][acol + 3][arow] = a0.w;
        As[buf][8 + acol + 0][arow] = a1.x;
        As[buf][8 + acol + 1][arow] = a1.y;
        As[buf][8 + acol + 2][arow] = a1.z;
        As[buf][8 + acol + 3][arow] = a1.w;
        *reinterpret_cast<float4*>(&Bs[buf][brow][bcol]) = b0;
        *reinterpret_cast<float4*>(&Bs[buf][brow + 8][bcol]) = b1;
    };
    auto compute = [&](int buf) {
#pragma unroll
        for (int k = 0; k < 16; k++) {
            float4 a0 = *reinterpret_cast<const float4*>(&As[buf][k][ty * 8]);
            float4 a1 = *reinterpret_cast<const float4*>(&As[buf][k][ty * 8 + 4]);
            float4 b0 = *reinterpret_cast<const float4*>(&Bs[buf][k][tx * 4]);
            float4 b1 = *reinterpret_cast<const float4*>(&Bs[buf][k][64 + tx * 4]);
            unsigned long long bp[4] = {
                pk2(b0.x, b0.y), pk2(b0.z, b0.w),
                pk2(b1.x, b1.y), pk2(b1.z, b1.w)
            };
            float a[8] = {a0.x, a0.y, a0.z, a0.w, a1.x, a1.y, a1.z, a1.w};
#pragma unroll
            for (int i = 0; i < 8; i++) {
                const unsigned long long ap = pk2(a[i], a[i]);
#pragma unroll
                for (int jp = 0; jp < 4; jp++)
                    ffma2(acc2[i][jp], ap, bp[jp]);
            }
        }
    };

    {
        float4 a0, a1, b0, b1;
        loadA(0, a0, a1);
        loadB(0, b0, b1);
        store(0, a0, a1, b0, b1);
    }
    __syncthreads();
    int cur = 0;
    for (int k0 = 16; k0 < K; k0 += 16) {
        float4 a0, a1, b0, b1;
        loadA(k0, a0, a1);
        loadB(k0, b0, b1);
        compute(cur);
        store(cur ^ 1, a0, a1, b0, b1);
        __syncthreads();
        cur ^= 1;
    }
    compute(cur);

    float acc[8][8];
#pragma unroll
    for (int i = 0; i < 8; i++)
#pragma unroll
        for (int jp = 0; jp < 4; jp++)
            unpk2(acc2[i][jp], acc[i][jp * 2], acc[i][jp * 2 + 1]);

#pragma unroll
    for (int i = 0; i < 8; i++) {
        const int m = bm + ty * 8 + i;
        if (m >= M) continue;
        float* crow = C + (size_t)m * N + bn;
        *reinterpret_cast<float4*>(crow + tx * 4) =
            make_float4(acc[i][0], acc[i][1], acc[i][2], acc[i][3]);
        *reinterpret_cast<float4*>(crow + 64 + tx * 4) =
            make_float4(acc[i][4], acc[i][5], acc[i][6], acc[i][7]);
    }

    if (ATT) {
        const int head = bn >> 7;
        float as_v[8], ad_v[8];
#pragma unroll
        for (int j = 0; j < 4; j++) {
            as_v[j]     = att_src[head * CH + tx * 4 + j];
            ad_v[j]     = att_dst[head * CH + tx * 4 + j];
            as_v[4 + j] = att_src[head * CH + 64 + tx * 4 + j];
            ad_v[4 + j] = att_dst[head * CH + 64 + tx * 4 + j];
        }
#pragma unroll
        for (int i = 0; i < 8; i++) {
            float s1 = 0.f, s2 = 0.f;
#pragma unroll
            for (int j = 0; j < 8; j++) {
                s1 = fmaf(acc[i][j], as_v[j], s1);
                s2 = fmaf(acc[i][j], ad_v[j], s2);
            }
#pragma unroll
            for (int o = 8; o >= 1; o >>= 1) {
                s1 += __shfl_xor_sync(0xffffffffu, s1, o);
                s2 += __shfl_xor_sync(0xffffffffu, s2, o);
            }
            const int m = bm + ty * 8 + i;
            if (tx == 0 && m < M) {
                g_asrc[m * 3 + head] = s1;
                g_adst[m * 3 + head] = s2;
            }
        }
    }
}

// ---------------- head GEMM: C[M,40] = relu(A)[M,384] @ B[384,40] + bias ----
__global__ __launch_bounds__(256) void sgemm_head_kernel(
    const float* __restrict__ A, const float* __restrict__ B,
    const float* __restrict__ bias, float* __restrict__ C, int M)
{
    const int NK = 384, NN = 40;
    __shared__ float As[8][128];
    __shared__ float Bs[8][40];
    const int tid = threadIdx.x;
    const int bm = blockIdx.x * 128;
    const int tx = tid & 7;
    const int ty = tid >> 3;
    const int arow = tid >> 1;
    const int acol = (tid & 1) << 2;
    const int gm = bm + arow;
    const bool avalid = (gm < M);

    float acc[4][5];
#pragma unroll
    for (int i = 0; i < 4; i++)
#pragma unroll
        for (int j = 0; j < 5; j++) acc[i][j] = 0.f;

    for (int k0 = 0; k0 < NK; k0 += 8) {
        float4 av = make_float4(0.f, 0.f, 0.f, 0.f);
        if (avalid)
            av = *reinterpret_cast<const float4*>(A + (size_t)gm * NK + k0 + acol);
        As[acol + 0][arow] = fmaxf(av.x, 0.f);
        As[acol + 1][arow] = fmaxf(av.y, 0.f);
        As[acol + 2][arow] = fmaxf(av.z, 0.f);
        As[acol + 3][arow] = fmaxf(av.w, 0.f);
        if (tid < 160) {
            const int r0 = tid / 20, c0 = (tid % 20) * 2;
            Bs[r0][c0]     = B[(size_t)(k0 + r0) * NN + c0];
            Bs[r0][c0 + 1] = B[(size_t)(k0 + r0) * NN + c0 + 1];
        }
        __syncthreads();
#pragma unroll
        for (int k = 0; k < 8; k++) {
            float a[4], b[5];
#pragma unroll
            for (int i = 0; i < 4; i++) a[i] = As[k][ty * 4 + i];
#pragma unroll
            for (int j = 0; j < 5; j++) b[j] = Bs[k][tx * 5 + j];
#pragma unroll
            for (int i = 0; i < 4; i++)
#pragma unroll
                for (int j = 0; j < 5; j++)
                    acc[i][j] = fmaf(a[i], b[j], acc[i][j]);
        }
        __syncthreads();
    }
#pragma unroll
    for (int i = 0; i < 4; i++) {
        const int m = bm + ty * 4 + i;
        if (m >= M) continue;
#pragma unroll
        for (int j = 0; j < 5; j++) {
            const int n = tx * 5 + j;
            C[(size_t)m * NN + n] = acc[i][j] + bias[n];
        }
    }
}

// ---------------- CSR build --------------------------------------------------
__global__ void zero_counts_kernel(int n)
{
    const int i = blockIdx.x * blockDim.x + threadIdx.x;
    if (i < n) g_counts[i] = 0;
}

__global__ void hist_kernel(const void* __restrict__ ei, int E, int ET)
{
    const int e = blockIdx.x * blockDim.x + threadIdx.x;
    if (e >= ET) return;
    const int d = (e < E) ? load_idx(ei, (size_t)E + e) : (e - E);
    atomicAdd(&g_counts[d], 1);
}

__global__ __launch_bounds__(1024) void scan1_kernel(int n)
{
    __shared__ int wsum[32];
    const int i = blockIdx.x * 1024 + threadIdx.x;
    const int lane = threadIdx.x & 31;
    const int wid = threadIdx.x >> 5;
    const int v = (i < n) ? g_counts[i] : 0;
    int x = v;
#pragma unroll
    for (int o = 1; o < 32; o <<= 1) {
        const int t = __shfl_up_sync(0xffffffffu, x, o);
        if (lane >= o) x += t;
    }
    if (lane == 31) wsum[wid] = x;
    __syncthreads();
    if (wid == 0) {
        int s = wsum[lane];
#pragma unroll
        for (int o = 1; o < 32; o <<= 1) {
            const int t = __shfl_up_sync(0xffffffffu, s, o);
            if (lane >= o) s += t;
        }
        wsum[lane] = s;
    }
    __syncthreads();
    const int incl = x + ((wid > 0) ? wsum[wid - 1] : 0);
    if (i < n) g_rowoff[i] = incl - v;
    if (threadIdx.x == 1023) g_bsum[blockIdx.x] = incl;
}

__global__ void scan2_kernel(int nb, int n)
{
    const int lane = threadIdx.x;
    const int a = (lane < nb) ? g_bsum[lane] : 0;
    const int b = (32 + lane < nb) ? g_bsum[32 + lane] : 0;
    int xa = a, xb = b;
#pragma unroll
    for (int o = 1; o < 32; o <<= 1) {
        int t = __shfl_up_sync(0xffffffffu, xa, o);
        if (lane >= o) xa += t;
        t = __shfl_up_sync(0xffffffffu, xb, o);
        if (lane >= o) xb += t;
    }
    const int totA = __shfl_sync(0xffffffffu, xa, 31);
    const int totB = __shfl_sync(0xffffffffu, xb, 31);
    g_boff[lane] = xa - a;
    g_boff[32 + lane] = totA + xb - b;
    if (lane == 31) g_rowoff[n] = totA + totB;
}

__global__ void scan3_kernel(int n)
{
    const int i = blockIdx.x * blockDim.x + threadIdx.x;
    if (i >= n) return;
    const int off = g_rowoff[i] + g_boff[i >> 10];
    g_rowoff[i] = off;
    g_cursor[i] = off;
}

__global__ void scatter_kernel(const void* __restrict__ ei, int E, int ET)
{
    const int e = blockIdx.x * blockDim.x + threadIdx.x;
    if (e >= ET) return;
    int s, d;
    if (e < E) { s = load_idx(ei, e); d = load_idx(ei, (size_t)E + e); }
    else       { s = d = e - E; }
    const int pos = atomicAdd(&g_cursor[d], 1);
    g_csr_s[pos] = s;
}

// ---------------- per-node softmax weights: one warp per node ---------------
// pass1: alpha=lrelu(asrc+adst) -> g_w (CSR order), warp max
// pass2: g_w = exp(alpha-max), warp sum -> g_denom
__global__ __launch_bounds__(256) void attn_kernel(int n_nodes)
{
    const int warp = (blockIdx.x * blockDim.x + threadIdx.x) >> 5;
    const int lane = threadIdx.x & 31;
    if (warp >= n_nodes) return;
    const int d = warp;
    const int beg = g_rowoff[d];
    const int end = g_rowoff[d + 1];
    const float ad0 = g_adst[d * 3 + 0];
    const float ad1 = g_adst[d * 3 + 1];
    const float ad2 = g_adst[d * 3 + 2];

    float m0 = -INFINITY, m1 = -INFINITY, m2 = -INFINITY;
    for (int i = beg + lane; i < end; i += 32) {
        const int s = g_csr_s[i];
        float a0 = g_asrc[s * 3 + 0] + ad0;
        float a1 = g_asrc[s * 3 + 1] + ad1;
        float a2 = g_asrc[s * 3 + 2] + ad2;
        a0 = (a0 > 0.f) ? a0 : 0.2f * a0;
        a1 = (a1 > 0.f) ? a1 : 0.2f * a1;
        a2 = (a2 > 0.f) ? a2 : 0.2f * a2;
        g_w[(size_t)i * 3 + 0] = a0;
        g_w[(size_t)i * 3 + 1] = a1;
        g_w[(size_t)i * 3 + 2] = a2;
        m0 = fmaxf(m0, a0); m1 = fmaxf(m1, a1); m2 = fmaxf(m2, a2);
    }
#pragma unroll
    for (int o = 16; o; o >>= 1) {
        m0 = fmaxf(m0, __shfl_xor_sync(0xffffffffu, m0, o));
        m1 = fmaxf(m1, __shfl_xor_sync(0xffffffffu, m1, o));
        m2 = fmaxf(m2, __shfl_xor_sync(0xffffffffu, m2, o));
    }
    float s0 = 0.f, s1 = 0.f, s2 = 0.f;
    for (int i = beg + lane; i < end; i += 32) {
        const float w0 = __expf(g_w[(size_t)i * 3 + 0] - m0);
        const float w1 = __expf(g_w[(size_t)i * 3 + 1] - m1);
        const float w2 = __expf(g_w[(size_t)i * 3 + 2] - m2);
        g_w[(size_t)i * 3 + 0] = w0;
        g_w[(size_t)i * 3 + 1] = w1;
        g_w[(size_t)i * 3 + 2] = w2;
        s0 += w0; s1 += w1; s2 += w2;
    }
#pragma unroll
    for (int o = 16; o; o >>= 1) {
        s0 += __shfl_xor_sync(0xffffffffu, s0, o);
        s1 += __shfl_xor_sync(0xffffffffu, s1, o);
        s2 += __shfl_xor_sync(0xffffffffu, s2, o);
    }
    if (lane == 0) {
        g_denom[d * 3 + 0] = s0;
        g_denom[d * 3 + 1] = s1;
        g_denom[d * 3 + 2] = s2;
    }
}

// ---------------- zero-sync weighted gather (4-way MLP, proven) -------------
__global__ __launch_bounds__(384) void gat_gather2(
    const float* __restrict__ P, const float* __restrict__ bias,
    float* __restrict__ out, int n_nodes)
{
    const int j = threadIdx.x;
    const int h = j >> 7;
    const float bj = bias[j];
    for (int d = blockIdx.x; d < n_nodes; d += gridDim.x) {
        const int beg = g_rowoff[d];
        const int end = g_rowoff[d + 1];
        const float inv = 1.f / (g_denom[d * 3 + h] + 1e-16f);
        float a0 = 0.f, a1 = 0.f, a2 = 0.f, a3 = 0.f;
        int i = beg;
        for (; i + 4 <= end; i += 4) {
            a0 = fmaf(g_w[(size_t)(i + 0) * 3 + h],
                      P[(size_t)g_csr_s[i + 0] * HC + j], a0);
            a1 = fmaf(g_w[(size_t)(i + 1) * 3 + h],
                      P[(size_t)g_csr_s[i + 1] * HC + j], a1);
            a2 = fmaf(g_w[(size_t)(i + 2) * 3 + h],
                      P[(size_t)g_csr_s[i + 2] * HC + j], a2);
            a3 = fmaf(g_w[(size_t)(i + 3) * 3 + h],
                      P[(size_t)g_csr_s[i + 3] * HC + j], a3);
        }
        for (; i < end; i++)
            a0 = fmaf(g_w[(size_t)i * 3 + h],
                      P[(size_t)g_csr_s[i] * HC + j], a0);
        out[(size_t)d * HC + j] = ((a0 + a1) + (a2 + a3)) * inv + bj;
    }
}

// ---------------- launch -----------------------------------------------------
extern "C" void kernel_launch(void* const* d_in, const int* in_sizes, int n_in,
                              void* d_out, int out_size)
{
    const float* x    = (const float*)d_in[0];
    const void*  ei   = d_in[1];
    const float* W1   = (const float*)d_in[2];
    const float* as1  = (const float*)d_in[3];
    const float* ad1  = (const float*)d_in[4];
    const float* b1   = (const float*)d_in[5];
    const float* W2   = (const float*)d_in[6];
    const float* as2  = (const float*)d_in[7];
    const float* ad2  = (const float*)d_in[8];
    const float* b2   = (const float*)d_in[9];
    const float* outW = (const float*)d_in[10];
    const float* outb = (const float*)d_in[11];
    float* out = (float*)d_out;

    const int IN_DIM = 256;
    const int n_nodes = in_sizes[0] / IN_DIM;   // 50000
    const int E  = in_sizes[1] / 2;             // 800000
    const int ET = E + n_nodes;                 // 850000

    float *p, *agg;
    cudaGetSymbolAddress((void**)&p,   g_p);
    cudaGetSymbolAddress((void**)&agg, g_agg);

    const int TB = 256;
    const int eg = (ET + TB - 1) / TB;
    const int nb = (n_nodes + 1023) / 1024;
    const int wg = (n_nodes * 32 + TB - 1) / TB;   // one warp per node

    const dim3 g12((HC + 127) / 128, (n_nodes + 127) / 128);

    // dtype probe (must precede any edge read)
    detect_dtype_kernel<<<1, 256>>>((const int*)ei);

    // CSR build start, then sgemm1 as 4th launch (fixed ncu window -s 5 -c 1
    // captures it there).
    zero_counts_kernel<<<(n_nodes + TB - 1) / TB, TB>>>(n_nodes);
    hist_kernel<<<eg, TB>>>(ei, E, ET);

    // ---- layer 1 GEMM (independent of CSR) ----
    sgemm_kernel<0, 1><<<g12, 256>>>(x, W1, p, as1, ad1, n_nodes, HC, IN_DIM);

    // rest of CSR build
    scan1_kernel<<<nb, 1024>>>(n_nodes);
    scan2_kernel<<<1, 32>>>(nb, n_nodes);
    scan3_kernel<<<(n_nodes + TB - 1) / TB, TB>>>(n_nodes);
    scatter_kernel<<<eg, TB>>>(ei, E, ET);

    // ---- layer 1 softmax + aggregate ----
    attn_kernel<<<wg, TB>>>(n_nodes);
    gat_gather2<<<n_nodes, 384>>>(p, b1, agg, n_nodes);

    // ---- layer 2 (relu fused into A-load of GEMM) ----
    sgemm_kernel<1, 1><<<g12, 256>>>(agg, W2, p, as2, ad2, n_nodes, HC, HC);
    attn_kernel<<<wg, TB>>>(n_nodes);
    gat_gather2<<<n_nodes, 384>>>(p, b2, agg, n_nodes);

    // ---- classifier head (relu fused into A-load) ----
    sgemm_head_kernel<<<(n_nodes + 127) / 128, 256>>>(agg, outW, outb, out, n_nodes);
}